// round 15
// baseline (speedup 1.0000x reference)
#include <cuda_runtime.h>
#include <cuda_bf16.h>
#include <cstdint>

#define NN   50000
#define EE   600000
#define FIN  128
#define HID  128
#define OUTC 64
#define EPSV 1e-9f

#define SCAN_B 256
#define SCAN_NB ((NN + SCAN_B - 1) / SCAN_B)   // 196

// ---------------- scratch (static device globals; no runtime allocation) ----
__device__ int   g_off [NN + 1];
__device__ int   g_cur [NN];
__device__ int   g_srcs[EE];
__device__ unsigned long long g_bstate[SCAN_NB];   // (flag<<62) | inclusive-val
__device__ __align__(16) float g_y[(size_t)NN * HID];
__device__ __align__(16) float g_z[(size_t)NN * OUTC];

// ---------------- threefry2x32, key = (0, 42) -------------------------------
__device__ __forceinline__ uint32_t tf_rotl(uint32_t x, int d) {
    return __funnelshift_l(x, x, d);
}

__device__ __forceinline__ uint32_t tf_bits32(uint32_t i) {
    const uint32_t k0 = 0u, k1 = 42u;
    const uint32_t k2 = 0u ^ 42u ^ 0x1BD11BDAu;
    uint32_t v0 = 0u + k0;
    uint32_t v1 = i  + k1;
#define TF_R(r) { v0 += v1; v1 = tf_rotl(v1, r); v1 ^= v0; }
    TF_R(13) TF_R(15) TF_R(26) TF_R(6)  v0 += k1; v1 += k2 + 1u;
    TF_R(17) TF_R(29) TF_R(16) TF_R(24) v0 += k2; v1 += k0 + 2u;
    TF_R(13) TF_R(15) TF_R(26) TF_R(6)  v0 += k0; v1 += k1 + 3u;
    TF_R(17) TF_R(29) TF_R(16) TF_R(24) v0 += k1; v1 += k2 + 4u;
    TF_R(13) TF_R(15) TF_R(26) TF_R(6)  v0 += k2; v1 += k0 + 5u;
#undef TF_R
    return v0 ^ v1;
}

__device__ __forceinline__ float drop_scale(uint32_t idx) {
    return (tf_bits32(idx) >> 31) ? 0.0f : 2.0f;
}

// ---------------- warp-MMA helpers (sm_80-era path; valid on compute_103) ---
__device__ __forceinline__ uint32_t smem_u32(const void* p) {
    uint32_t a;
    asm("{ .reg .u64 t; cvta.to.shared.u64 t, %1; cvt.u32.u64 %0, t; }"
        : "=r"(a) : "l"(p));
    return a;
}

#define LDSM_X4(r0, r1, r2, r3, addr) \
    asm volatile("ldmatrix.sync.aligned.m8n8.x4.shared.b16 {%0,%1,%2,%3}, [%4];" \
        : "=r"(r0), "=r"(r1), "=r"(r2), "=r"(r3) : "r"(addr))

#define MMA_BF16(d, a, b0, b1) \
    asm volatile("mma.sync.aligned.m16n8k16.row.col.f32.bf16.bf16.f32 " \
        "{%0,%1,%2,%3}, {%4,%5,%6,%7}, {%8,%9}, {%0,%1,%2,%3};" \
        : "+f"((d)[0]), "+f"((d)[1]), "+f"((d)[2]), "+f"((d)[3]) \
        : "r"((a)[0]), "r"((a)[1]), "r"((a)[2]), "r"((a)[3]), \
          "r"(b0), "r"(b1))

__device__ __forceinline__ uint32_t bf16pack(float a, float b) {
    return ((uint32_t)__bfloat16_as_ushort(__float2bfloat16(b)) << 16)
         |  (uint32_t)__bfloat16_as_ushort(__float2bfloat16(a));
}
__device__ __forceinline__ float bf16res(float v) {
    return v - __bfloat162float(__float2bfloat16(v));
}

// ---------------- CSR build (edge_index is int32: src=[0,E), dst=[E,2E)) ---
__global__ void zero_kernel() {
    int i = blockIdx.x * blockDim.x + threadIdx.x;
    if (i < NN) g_cur[i] = 0;
    if (i < SCAN_NB) g_bstate[i] = 0ull;
}

__global__ void hist_kernel(const int* __restrict__ ei) {
    int e = blockIdx.x * blockDim.x + threadIdx.x;
    if (e < EE) atomicAdd(&g_cur[ei[EE + e]], 1);
}

// ---- single-kernel decoupled-lookback exclusive scan of g_cur --------------
__global__ void scan_lookback_kernel() {
    __shared__ int wpre[8];
    __shared__ int s_excl;
    int b = blockIdx.x;
    int i = b * SCAN_B + threadIdx.x;
    int v = (i < NN) ? g_cur[i] : 0;
    int lane = threadIdx.x & 31, w = threadIdx.x >> 5;
    int inc = v;
    #pragma unroll
    for (int o = 1; o < 32; o <<= 1) {
        int u = __shfl_up_sync(0xffffffffu, inc, o);
        if (lane >= o) inc += u;
    }
    if (lane == 31) wpre[w] = inc;
    __syncthreads();
    if (w == 0) {
        int s = (lane < 8) ? wpre[lane] : 0;
        int si = s;
        #pragma unroll
        for (int o = 1; o < 8; o <<= 1) {
            int u = __shfl_up_sync(0xffffffffu, si, o);
            if (lane >= o) si += u;
        }
        if (lane < 8) wpre[lane] = si - s;   // exclusive warp prefix
        if (lane == 7) {                     // si = block total here
            int bsum = si;
            int excl = 0;
            if (b == 0) {
                atomicExch(&g_bstate[0], (2ull << 62) | (unsigned long long)(uint32_t)bsum);
            } else {
                atomicExch(&g_bstate[b], (1ull << 62) | (unsigned long long)(uint32_t)bsum);
                int j = b - 1;
                for (;;) {
                    unsigned long long st;
                    do { st = atomicAdd(&g_bstate[j], 0ull); } while ((st >> 62) == 0ull);
                    int val = (int)(uint32_t)st;
                    excl += val;
                    if ((st >> 62) == 2ull) break;
                    j--;
                }
                atomicExch(&g_bstate[b],
                            (2ull << 62) | (unsigned long long)(uint32_t)(excl + bsum));
            }
            s_excl = excl;
            if (b == SCAN_NB - 1) g_off[NN] = excl + bsum;
        }
    }
    __syncthreads();
    if (i < NN) {
        int o = s_excl + wpre[w] + (inc - v);
        g_off[i] = o;
        g_cur[i] = o;
    }
}

__global__ void bucket_kernel(const int* __restrict__ ei) {
    int e = blockIdx.x * blockDim.x + threadIdx.x;
    if (e < EE) {
        int d = ei[EE + e];
        int p = atomicAdd(&g_cur[d], 1);
        g_srcs[p] = ei[e];
    }
}

// ---------------- GEMM1 via mma.sync bf16 hi/lo split -----------------------
// CTA: 64 rows x 128 cols, K=128. 8 warps = 4(M) x 2(N); warp = 16x64.
// smem pitch 272B -> ldmatrix row-groups bank-conflict-free.
#define MMA_PITCH 272
__global__ void __launch_bounds__(256)
mma_gemm1_kernel(const float* __restrict__ x, const float* __restrict__ W1) {
    extern __shared__ char smem[];
    const int A_HI = 0, A_LO = 17408, B_HI = 34816, B_LO = 69632;
    uint32_t sb = smem_u32(smem);
    int t = threadIdx.x, lane = t & 31, w = t >> 5;
    int rowBase = blockIdx.x * 64;

    for (int i = t; i < 16384; i += 256) {        // B = W1^T hi/lo
        int k = i >> 7, n = i & 127;
        float v = W1[i];
        float r = bf16res(v);
        *(__nv_bfloat16*)(smem + B_HI + n * MMA_PITCH + k * 2) = __float2bfloat16(v);
        *(__nv_bfloat16*)(smem + B_LO + n * MMA_PITCH + k * 2) = __float2bfloat16(r);
    }
    for (int i = t; i < 8192; i += 256) {         // A rows hi/lo
        int m = i >> 7, k = i & 127;
        int gr = rowBase + m;
        float v = (gr < NN) ? x[(size_t)gr * 128 + k] : 0.0f;
        float r = bf16res(v);
        *(__nv_bfloat16*)(smem + A_HI + m * MMA_PITCH + k * 2) = __float2bfloat16(v);
        *(__nv_bfloat16*)(smem + A_LO + m * MMA_PITCH + k * 2) = __float2bfloat16(r);
    }
    __syncthreads();

    int wm = w & 3, wn = w >> 2;
    float acc[8][4];
    #pragma unroll
    for (int j = 0; j < 8; j++)
        #pragma unroll
        for (int c = 0; c < 4; c++) acc[j][c] = 0.0f;

    uint32_t aRow = (uint32_t)(wm * 16 + (lane & 7) + ((lane >> 3) & 1) * 8);
    uint32_t aOff = aRow * MMA_PITCH + (uint32_t)(lane >> 4) * 16u;
    uint32_t aHiA = sb + A_HI + aOff;
    uint32_t aLoA = sb + A_LO + aOff;
    uint32_t bg = lane >> 3, br = lane & 7;
    uint32_t bRowOff = ((bg >> 1) * 8u + br) * MMA_PITCH + (bg & 1u) * 16u;

    #pragma unroll
    for (int ks = 0; ks < 8; ks++) {
        uint32_t k2 = (uint32_t)ks * 32u;
        uint32_t ah[4], al[4];
        LDSM_X4(ah[0], ah[1], ah[2], ah[3], aHiA + k2);
        LDSM_X4(al[0], al[1], al[2], al[3], aLoA + k2);
        #pragma unroll
        for (int jj = 0; jj < 4; jj++) {
            uint32_t nOff = (uint32_t)(wn * 64 + jj * 16) * MMA_PITCH;
            uint32_t bh[4], bl[4];
            LDSM_X4(bh[0], bh[1], bh[2], bh[3], sb + B_HI + nOff + bRowOff + k2);
            LDSM_X4(bl[0], bl[1], bl[2], bl[3], sb + B_LO + nOff + bRowOff + k2);
            MMA_BF16(acc[2 * jj],     ah, bh[0], bh[1]);
            MMA_BF16(acc[2 * jj],     ah, bl[0], bl[1]);
            MMA_BF16(acc[2 * jj],     al, bh[0], bh[1]);
            MMA_BF16(acc[2 * jj + 1], ah, bh[2], bh[3]);
            MMA_BF16(acc[2 * jj + 1], ah, bl[2], bl[3]);
            MMA_BF16(acc[2 * jj + 1], al, bh[2], bh[3]);
        }
    }

    int r0 = rowBase + wm * 16 + (lane >> 2);
    int col = wn * 64 + (lane & 3) * 2;
    #pragma unroll
    for (int j = 0; j < 8; j++) {
        if (r0 < NN)
            *(float2*)&g_y[(size_t)r0 * 128 + col + j * 8] =
                make_float2(acc[j][0], acc[j][1]);
        if (r0 + 8 < NN)
            *(float2*)&g_y[(size_t)(r0 + 8) * 128 + col + j * 8] =
                make_float2(acc[j][2], acc[j][3]);
    }
}

// ---------------- FUSED: agg1 (gather+relu+dropout) -> mma GEMM2 ------------
// CTA = 64 nodes. Phase 1: warp w gathers rows [w*8, w*8+8), splits hi/lo
// straight into the mma A-tiles. Phase 2: z tile = Hs @ W2 via mma.sync.
__global__ void __launch_bounds__(256)
fused_agg_mma2_kernel(const float* __restrict__ b1, const float* __restrict__ W2) {
    extern __shared__ char smem[];
    const int A_HI = 0, A_LO = 17408, B_HI = 34816, B_LO = 52224;
    uint32_t sb = smem_u32(smem);
    int t = threadIdx.x, lane = t & 31, w = t >> 5;
    int rowBase = blockIdx.x * 64;

    // B = W2^T hi/lo (8192 floats)
    for (int i = t; i < 8192; i += 256) {
        int k = i >> 6, n = i & 63;
        float v = W2[i];
        float r = bf16res(v);
        *(__nv_bfloat16*)(smem + B_HI + n * MMA_PITCH + k * 2) = __float2bfloat16(v);
        *(__nv_bfloat16*)(smem + B_LO + n * MMA_PITCH + k * 2) = __float2bfloat16(r);
    }

    // phase 1: gather + bias + ReLU + dropout -> hi/lo into A tiles
    {
        const float4* Y = (const float4*)g_y;
        float4 bb = ((const float4*)b1)[lane];
        const float c1 = 1.0f + EPSV;
        #pragma unroll 1
        for (int i = 0; i < 8; i++) {
            int node = rowBase + w * 8 + i;
            float4 acc = make_float4(0.f, 0.f, 0.f, 0.f);
            if (node < NN) {
                acc = Y[(size_t)node * 32 + lane];
                acc.x = fmaf(acc.x, c1, bb.x);
                acc.y = fmaf(acc.y, c1, bb.y);
                acc.z = fmaf(acc.z, c1, bb.z);
                acc.w = fmaf(acc.w, c1, bb.w);

                int j = g_off[node], end = g_off[node + 1];
                for (; j + 4 <= end; j += 4) {
                    int s0 = g_srcs[j], s1 = g_srcs[j + 1];
                    int s2 = g_srcs[j + 2], s3 = g_srcs[j + 3];
                    float4 v0 = Y[(size_t)s0 * 32 + lane];
                    float4 v1 = Y[(size_t)s1 * 32 + lane];
                    float4 v2 = Y[(size_t)s2 * 32 + lane];
                    float4 v3 = Y[(size_t)s3 * 32 + lane];
                    acc.x += (v0.x + v1.x) + (v2.x + v3.x);
                    acc.y += (v0.y + v1.y) + (v2.y + v3.y);
                    acc.z += (v0.z + v1.z) + (v2.z + v3.z);
                    acc.w += (v0.w + v1.w) + (v2.w + v3.w);
                }
                for (; j < end; j++) {
                    float4 v = Y[(size_t)g_srcs[j] * 32 + lane];
                    acc.x += v.x; acc.y += v.y; acc.z += v.z; acc.w += v.w;
                }

                acc.x = fmaxf(acc.x, 0.f);
                acc.y = fmaxf(acc.y, 0.f);
                acc.z = fmaxf(acc.z, 0.f);
                acc.w = fmaxf(acc.w, 0.f);

                uint32_t base = (uint32_t)node * 128u + (uint32_t)lane * 4u;
                acc.x *= drop_scale(base + 0u);
                acc.y *= drop_scale(base + 1u);
                acc.z *= drop_scale(base + 2u);
                acc.w *= drop_scale(base + 3u);
            }
            int m = w * 8 + i;
            uint32_t off = (uint32_t)m * MMA_PITCH + (uint32_t)lane * 8u;
            *(uint2*)(smem + A_HI + off) =
                make_uint2(bf16pack(acc.x, acc.y), bf16pack(acc.z, acc.w));
            *(uint2*)(smem + A_LO + off) =
                make_uint2(bf16pack(bf16res(acc.x), bf16res(acc.y)),
                           bf16pack(bf16res(acc.z), bf16res(acc.w)));
        }
    }
    __syncthreads();

    // phase 2: z = Hs @ W2 (NC=64: warp = 16x32, JJ=2)
    int wm = w & 3, wn = w >> 2;
    float acc[4][4];
    #pragma unroll
    for (int j = 0; j < 4; j++)
        #pragma unroll
        for (int c = 0; c < 4; c++) acc[j][c] = 0.0f;

    uint32_t aRow = (uint32_t)(wm * 16 + (lane & 7) + ((lane >> 3) & 1) * 8);
    uint32_t aOff = aRow * MMA_PITCH + (uint32_t)(lane >> 4) * 16u;
    uint32_t aHiA = sb + A_HI + aOff;
    uint32_t aLoA = sb + A_LO + aOff;
    uint32_t bg = lane >> 3, br = lane & 7;
    uint32_t bRowOff = ((bg >> 1) * 8u + br) * MMA_PITCH + (bg & 1u) * 16u;

    #pragma unroll
    for (int ks = 0; ks < 8; ks++) {
        uint32_t k2 = (uint32_t)ks * 32u;
        uint32_t ah[4], al[4];
        LDSM_X4(ah[0], ah[1], ah[2], ah[3], aHiA + k2);
        LDSM_X4(al[0], al[1], al[2], al[3], aLoA + k2);
        #pragma unroll
        for (int jj = 0; jj < 2; jj++) {
            uint32_t nOff = (uint32_t)(wn * 32 + jj * 16) * MMA_PITCH;
            uint32_t bh[4], bl[4];
            LDSM_X4(bh[0], bh[1], bh[2], bh[3], sb + B_HI + nOff + bRowOff + k2);
            LDSM_X4(bl[0], bl[1], bl[2], bl[3], sb + B_LO + nOff + bRowOff + k2);
            MMA_BF16(acc[2 * jj],     ah, bh[0], bh[1]);
            MMA_BF16(acc[2 * jj],     ah, bl[0], bl[1]);
            MMA_BF16(acc[2 * jj],     al, bh[0], bh[1]);
            MMA_BF16(acc[2 * jj + 1], ah, bh[2], bh[3]);
            MMA_BF16(acc[2 * jj + 1], ah, bl[2], bl[3]);
            MMA_BF16(acc[2 * jj + 1], al, bh[2], bh[3]);
        }
    }

    int r0 = rowBase + wm * 16 + (lane >> 2);
    int col = wn * 32 + (lane & 3) * 2;
    #pragma unroll
    for (int j = 0; j < 4; j++) {
        if (r0 < NN)
            *(float2*)&g_z[(size_t)r0 * 64 + col + j * 8] =
                make_float2(acc[j][0], acc[j][1]);
        if (r0 + 8 < NN)
            *(float2*)&g_z[(size_t)(r0 + 8) * 64 + col + j * 8] =
                make_float2(acc[j][2], acc[j][3]);
    }
}

// ---------------- layer-2 aggregate + bias -> output -----------------------
__global__ void __launch_bounds__(256)
agg_out_kernel(const float* __restrict__ b2, float* __restrict__ out) {
    int gw = (blockIdx.x * blockDim.x + threadIdx.x) >> 5;
    if (gw >= NN) return;
    int lane = threadIdx.x & 31;

    const float2* Z = (const float2*)g_z;
    float2 acc = Z[(size_t)gw * 32 + lane];
    float2 bb  = ((const float2*)b2)[lane];
    const float c1 = 1.0f + EPSV;
    acc.x = fmaf(acc.x, c1, bb.x);
    acc.y = fmaf(acc.y, c1, bb.y);

    int j = g_off[gw], end = g_off[gw + 1];
    for (; j + 4 <= end; j += 4) {
        int s0 = g_srcs[j], s1 = g_srcs[j + 1], s2 = g_srcs[j + 2], s3 = g_srcs[j + 3];
        float2 v0 = Z[(size_t)s0 * 32 + lane];
        float2 v1 = Z[(size_t)s1 * 32 + lane];
        float2 v2 = Z[(size_t)s2 * 32 + lane];
        float2 v3 = Z[(size_t)s3 * 32 + lane];
        acc.x += (v0.x + v1.x) + (v2.x + v3.x);
        acc.y += (v0.y + v1.y) + (v2.y + v3.y);
    }
    for (; j < end; j++) {
        float2 v = Z[(size_t)g_srcs[j] * 32 + lane];
        acc.x += v.x; acc.y += v.y;
    }

    ((float2*)out)[(size_t)gw * 32 + lane] = acc;
}

// ---------------- launch -----------------------------------------------------
extern "C" void kernel_launch(void* const* d_in, const int* in_sizes, int n_in,
                              void* d_out, int out_size) {
    const float* x  = (const float*)d_in[0];
    const int*   ei = (const int*)d_in[1];     // int32 (JAX x64 disabled)
    const float* W1 = (const float*)d_in[2];
    const float* b1 = (const float*)d_in[3];
    const float* W2 = (const float*)d_in[4];
    const float* b2 = (const float*)d_in[5];
    float*       out = (float*)d_out;

    const int SMEM1 = 104448;   // A hi/lo (2x17408) + B hi/lo (2x34816)
    const int SMEM2 = 69632;    // A hi/lo + B hi/lo (4x17408)
    cudaFuncSetAttribute(mma_gemm1_kernel,
                         cudaFuncAttributeMaxDynamicSharedMemorySize, SMEM1);
    cudaFuncSetAttribute(fused_agg_mma2_kernel,
                         cudaFuncAttributeMaxDynamicSharedMemorySize, SMEM2);

    // ONE side stream + events (capture-safe fork/join; not destroyed —
    // destroying during active capture invalidates it; stays in driver pool).
    cudaStream_t s2;
    cudaStreamCreate(&s2);
    cudaEvent_t eFork, eCSR;
    cudaEventCreateWithFlags(&eFork, cudaEventDisableTiming);
    cudaEventCreateWithFlags(&eCSR,  cudaEventDisableTiming);

    cudaEventRecord(eFork, 0);
    cudaStreamWaitEvent(s2, eFork, 0);

    // branch A (s2): CSR build (4 kernels)
    zero_kernel<<<(NN + 255) / 256, 256, 0, s2>>>();
    hist_kernel<<<(EE + 255) / 256, 256, 0, s2>>>(ei);
    scan_lookback_kernel<<<SCAN_NB, SCAN_B, 0, s2>>>();
    bucket_kernel<<<(EE + 255) / 256, 256, 0, s2>>>(ei);
    cudaEventRecord(eCSR, s2);

    // branch B (default): y = x@W1 on tensor cores (mma.sync bf16 hi/lo)
    mma_gemm1_kernel<<<(NN + 63) / 64, 256, SMEM1>>>(x, W1);

    // join
    cudaStreamWaitEvent(0, eCSR, 0);

    // fused: h = dropout(relu((1+eps)y + seg_sum(y[src]) + b1)); z = h@W2
    fused_agg_mma2_kernel<<<(NN + 63) / 64, 256, SMEM2>>>(b1, W2);

    // final: out = (1+eps)z + seg_sum(z[src]) + b2
    agg_out_kernel<<<(NN * 32 + 255) / 256, 256>>>(b2, out);
}